// round 3
// baseline (speedup 1.0000x reference)
#include <cuda_runtime.h>
#include <cstdint>

#define NB 2
#define NH 12
#define SQ 2048
#define DH 64
#define DM 768
#define SCALE 0.125f

// Scratch for Q/K/V in [B, H, S, Dh] layout (device globals: allocation-free rule)
__device__ float g_q[NB * NH * SQ * DH];
__device__ float g_k[NB * NH * SQ * DH];
__device__ float g_v[NB * NH * SQ * DH];

__device__ __forceinline__ uint32_t f2tf(float f) {
    uint32_t u;
    asm("cvt.rna.tf32.f32 %0, %1;" : "=r"(u) : "f"(f));
    return u;
}

__device__ __forceinline__ void mma8(float* c, const uint32_t* a, const uint32_t* b) {
    asm volatile(
        "mma.sync.aligned.m16n8k8.row.col.f32.tf32.tf32.f32 "
        "{%0,%1,%2,%3}, {%4,%5,%6,%7}, {%8,%9}, {%0,%1,%2,%3};\n"
        : "+f"(c[0]), "+f"(c[1]), "+f"(c[2]), "+f"(c[3])
        : "r"(a[0]), "r"(a[1]), "r"(a[2]), "r"(a[3]), "r"(b[0]), "r"(b[1]));
}

// ---------------------------------------------------------------------------
// Kernel 1: fused QKV projection.  out[m,n] = X[m,:] . W[n,:] + bias[n]
// M=4096 (b*s), N=768, K=768.  BM=128, BN=64, BK=32. 8 warps (4x2), warp 32x32.
// blockIdx.z selects {Q,K,V}; stores into [B,H,S,Dh] scratch.
// ---------------------------------------------------------------------------
__global__ __launch_bounds__(256) void qkv_kernel(
    const float* __restrict__ X,
    const float* __restrict__ Wq, const float* __restrict__ bq,
    const float* __restrict__ Wk, const float* __restrict__ bk,
    const float* __restrict__ Wv, const float* __restrict__ bv)
{
    const float* W;
    const float* bias;
    float* out;
    if (blockIdx.z == 0)      { W = Wq; bias = bq; out = g_q; }
    else if (blockIdx.z == 1) { W = Wk; bias = bk; out = g_k; }
    else                      { W = Wv; bias = bv; out = g_v; }

    __shared__ uint32_t As[128][36];  // [m][k], tf32 bits, pad 4
    __shared__ uint32_t Bs[64][36];   // [n][k], tf32 bits

    const int tid  = threadIdx.x;
    const int lane = tid & 31;
    const int warp = tid >> 5;
    const int wm   = warp >> 1;   // 0..3
    const int wn   = warp & 1;    // 0..1
    const int m0   = blockIdx.y * 128;
    const int n0   = blockIdx.x * 64;

    float acc[2][4][4];
    #pragma unroll
    for (int i = 0; i < 2; i++)
        #pragma unroll
        for (int j = 0; j < 4; j++)
            #pragma unroll
            for (int e = 0; e < 4; e++) acc[i][j][e] = 0.f;

    const int ar = tid >> 3;        // 0..31
    const int ac = (tid & 7) * 4;   // 0..28

    for (int kt = 0; kt < DM / 32; kt++) {
        const int k0 = kt * 32;
        #pragma unroll
        for (int it = 0; it < 4; it++) {
            int r = ar + it * 32;
            float4 v = *(const float4*)&X[(size_t)(m0 + r) * DM + k0 + ac];
            *(uint4*)&As[r][ac] = make_uint4(f2tf(v.x), f2tf(v.y), f2tf(v.z), f2tf(v.w));
        }
        #pragma unroll
        for (int it = 0; it < 2; it++) {
            int r = ar + it * 32;
            float4 v = *(const float4*)&W[(size_t)(n0 + r) * DM + k0 + ac];
            *(uint4*)&Bs[r][ac] = make_uint4(f2tf(v.x), f2tf(v.y), f2tf(v.z), f2tf(v.w));
        }
        __syncthreads();
        #pragma unroll
        for (int kk = 0; kk < 4; kk++) {
            uint32_t a[2][4], b[4][2];
            #pragma unroll
            for (int i = 0; i < 2; i++) {
                int r = wm * 32 + i * 16 + (lane >> 2);
                int c = kk * 8 + (lane & 3);
                a[i][0] = As[r][c];
                a[i][1] = As[r + 8][c];
                a[i][2] = As[r][c + 4];
                a[i][3] = As[r + 8][c + 4];
            }
            #pragma unroll
            for (int j = 0; j < 4; j++) {
                int cc = wn * 32 + j * 8 + (lane >> 2);
                int c  = kk * 8 + (lane & 3);
                b[j][0] = Bs[cc][c];
                b[j][1] = Bs[cc][c + 4];
            }
            #pragma unroll
            for (int i = 0; i < 2; i++)
                #pragma unroll
                for (int j = 0; j < 4; j++)
                    mma8(acc[i][j], a[i], b[j]);
        }
        __syncthreads();
    }

    // Epilogue: +bias, store to [B,H,S,Dh]
    #pragma unroll
    for (int i = 0; i < 2; i++) {
        #pragma unroll
        for (int j = 0; j < 4; j++) {
            int n  = n0 + wn * 32 + j * 8 + 2 * (lane & 3);
            int h  = n >> 6;
            int dh = n & 63;
            float b0 = bias[n], b1 = bias[n + 1];
            #pragma unroll
            for (int rr = 0; rr < 2; rr++) {
                int m  = m0 + wm * 32 + i * 16 + (lane >> 2) + rr * 8;
                int bb = m >> 11;       // batch
                int s  = m & 2047;      // seq
                size_t idx = (((size_t)(bb * NH + h)) * SQ + s) * DH + dh;
                out[idx]     = acc[i][j][rr * 2 + 0] + b0;
                out[idx + 1] = acc[i][j][rr * 2 + 1] + b1;
            }
        }
    }
}

// ---------------------------------------------------------------------------
// Kernel 2: flash-style attention with RealFormer residual.
// Grid: (S/128, H, B). 8 warps; warp w owns q rows [128*bx + 16w, +16).
// Per 32-key chunk: S = Q.K^T*scale + res (write res_out), += mask,
// online softmax, O += P.V.
// ---------------------------------------------------------------------------
__global__ __launch_bounds__(256, 2) void attn_kernel(
    const float* __restrict__ res_in,
    const float* __restrict__ mask,
    float* __restrict__ ctx_out,
    float* __restrict__ res_out)
{
    __shared__ uint32_t sK[32][68];       // [key][dh] tf32 bits
    __shared__ uint32_t sV[32][68];       // [key][dh] tf32 bits
    __shared__ uint32_t sP[8][16][36];    // per-warp P tile, tf32 bits

    const int tid  = threadIdx.x;
    const int lane = tid & 31;
    const int warp = tid >> 5;
    const int h  = blockIdx.y;
    const int b  = blockIdx.z;
    const int bh = b * NH + h;
    const int q0 = blockIdx.x * 128;

    const float* Q = g_q + (size_t)bh * SQ * DH;
    const float* K = g_k + (size_t)bh * SQ * DH;
    const float* V = g_v + (size_t)bh * SQ * DH;

    // Q fragments, register-resident for whole block (k = 64 -> 8 k-steps)
    uint32_t qf[8][4];
    {
        int r0 = q0 + warp * 16 + (lane >> 2);
        const float* Qr0 = Q + (size_t)r0 * DH;
        const float* Qr8 = Q + (size_t)(r0 + 8) * DH;
        #pragma unroll
        for (int kk = 0; kk < 8; kk++) {
            int c = kk * 8 + (lane & 3);
            qf[kk][0] = f2tf(Qr0[c]);
            qf[kk][1] = f2tf(Qr8[c]);
            qf[kk][2] = f2tf(Qr0[c + 4]);
            qf[kk][3] = f2tf(Qr8[c + 4]);
        }
    }

    float Oacc[8][4];
    #pragma unroll
    for (int f = 0; f < 8; f++)
        #pragma unroll
        for (int e = 0; e < 4; e++) Oacc[f][e] = 0.f;
    float mrow0 = -1e30f, mrow1 = -1e30f;
    float lrow0 = 0.f, lrow1 = 0.f;

    const int rq0 = q0 + warp * 16 + (lane >> 2);
    const size_t res_base0 = ((size_t)bh * SQ + rq0) * SQ;
    const size_t res_base8 = res_base0 + (size_t)8 * SQ;
    const float* mrk = mask + b * SQ;

    for (int j = 0; j < SQ / 32; j++) {
        const int kb = j * 32;
        __syncthreads();   // previous chunk's reads of sK/sV done
        // Load K,V chunk (32 keys x 64 dh each), coalesced float4
        {
            int r = tid >> 4;           // 0..15
            int c = (tid & 15) * 4;     // 0..60
            #pragma unroll
            for (int it = 0; it < 2; it++) {
                int key = r + it * 16;
                float4 kv = *(const float4*)&K[(size_t)(kb + key) * DH + c];
                *(uint4*)&sK[key][c] = make_uint4(f2tf(kv.x), f2tf(kv.y), f2tf(kv.z), f2tf(kv.w));
                float4 vv = *(const float4*)&V[(size_t)(kb + key) * DH + c];
                *(uint4*)&sV[key][c] = make_uint4(f2tf(vv.x), f2tf(vv.y), f2tf(vv.z), f2tf(vv.w));
            }
        }
        __syncthreads();

        // S = Q . K^T  (m16 x n32, k=64)
        float s[4][4];
        #pragma unroll
        for (int f = 0; f < 4; f++)
            #pragma unroll
            for (int e = 0; e < 4; e++) s[f][e] = 0.f;
        #pragma unroll
        for (int kk = 0; kk < 8; kk++) {
            uint32_t bfr[4][2];
            int c = kk * 8 + (lane & 3);
            #pragma unroll
            for (int f = 0; f < 4; f++) {
                int key = f * 8 + (lane >> 2);
                bfr[f][0] = sK[key][c];
                bfr[f][1] = sK[key][c + 4];
            }
            #pragma unroll
            for (int f = 0; f < 4; f++) mma8(s[f], qf[kk], bfr[f]);
        }

        // scale + residual, write scores_res_out (pre-mask), then + mask
        #pragma unroll
        for (int f = 0; f < 4; f++) {
            int col = kb + f * 8 + 2 * (lane & 3);
            float2 r0v = *(const float2*)&res_in[res_base0 + col];
            float2 r8v = *(const float2*)&res_in[res_base8 + col];
            s[f][0] = s[f][0] * SCALE + r0v.x;
            s[f][1] = s[f][1] * SCALE + r0v.y;
            s[f][2] = s[f][2] * SCALE + r8v.x;
            s[f][3] = s[f][3] * SCALE + r8v.y;
            *(float2*)&res_out[res_base0 + col] = make_float2(s[f][0], s[f][1]);
            *(float2*)&res_out[res_base8 + col] = make_float2(s[f][2], s[f][3]);
            float2 mk = *(const float2*)&mrk[col];
            s[f][0] += mk.x; s[f][1] += mk.y;
            s[f][2] += mk.x; s[f][3] += mk.y;
        }

        // online softmax (rows owned within a quad: shfl xor 1,2)
        float cmax0 = -1e30f, cmax1 = -1e30f;
        #pragma unroll
        for (int f = 0; f < 4; f++) {
            cmax0 = fmaxf(cmax0, fmaxf(s[f][0], s[f][1]));
            cmax1 = fmaxf(cmax1, fmaxf(s[f][2], s[f][3]));
        }
        cmax0 = fmaxf(cmax0, __shfl_xor_sync(0xffffffff, cmax0, 1));
        cmax0 = fmaxf(cmax0, __shfl_xor_sync(0xffffffff, cmax0, 2));
        cmax1 = fmaxf(cmax1, __shfl_xor_sync(0xffffffff, cmax1, 1));
        cmax1 = fmaxf(cmax1, __shfl_xor_sync(0xffffffff, cmax1, 2));
        float nm0 = fmaxf(mrow0, cmax0);
        float nm1 = fmaxf(mrow1, cmax1);
        float corr0 = __expf(mrow0 - nm0);
        float corr1 = __expf(mrow1 - nm1);
        mrow0 = nm0; mrow1 = nm1;

        float sum0 = 0.f, sum1 = 0.f;
        #pragma unroll
        for (int f = 0; f < 4; f++) {
            s[f][0] = __expf(s[f][0] - nm0);
            s[f][1] = __expf(s[f][1] - nm0);
            s[f][2] = __expf(s[f][2] - nm1);
            s[f][3] = __expf(s[f][3] - nm1);
            sum0 += s[f][0] + s[f][1];
            sum1 += s[f][2] + s[f][3];
        }
        sum0 += __shfl_xor_sync(0xffffffff, sum0, 1);
        sum0 += __shfl_xor_sync(0xffffffff, sum0, 2);
        sum1 += __shfl_xor_sync(0xffffffff, sum1, 1);
        sum1 += __shfl_xor_sync(0xffffffff, sum1, 2);
        lrow0 = lrow0 * corr0 + sum0;
        lrow1 = lrow1 * corr1 + sum1;
        #pragma unroll
        for (int f = 0; f < 8; f++) {
            Oacc[f][0] *= corr0; Oacc[f][1] *= corr0;
            Oacc[f][2] *= corr1; Oacc[f][3] *= corr1;
        }

        // P -> smem (tf32) for A-fragment re-layout
        #pragma unroll
        for (int f = 0; f < 4; f++) {
            int c = f * 8 + 2 * (lane & 3);
            int g = lane >> 2;
            sP[warp][g][c]         = f2tf(s[f][0]);
            sP[warp][g][c + 1]     = f2tf(s[f][1]);
            sP[warp][g + 8][c]     = f2tf(s[f][2]);
            sP[warp][g + 8][c + 1] = f2tf(s[f][3]);
        }
        __syncwarp();

        // O += P . V  (k = 32 keys -> 4 k-steps, n = 64 dh -> 8 frags)
        #pragma unroll
        for (int kk = 0; kk < 4; kk++) {
            uint32_t a[4];
            int g  = lane >> 2;
            int pc = kk * 8 + (lane & 3);
            a[0] = sP[warp][g][pc];
            a[1] = sP[warp][g + 8][pc];
            a[2] = sP[warp][g][pc + 4];
            a[3] = sP[warp][g + 8][pc + 4];
            int kr = kk * 8 + (lane & 3);
            #pragma unroll
            for (int f = 0; f < 8; f++) {
                uint32_t bb[2];
                int nc = f * 8 + (lane >> 2);
                bb[0] = sV[kr][nc];
                bb[1] = sV[kr + 4][nc];
                mma8(Oacc[f], a, bb);
            }
        }
    }

    // Epilogue: O / l, store ctx [B, S, H*Dh]
    float inv0 = 1.f / lrow0;
    float inv1 = 1.f / lrow1;
    int row0 = q0 + warp * 16 + (lane >> 2);
    #pragma unroll
    for (int f = 0; f < 8; f++) {
        int dh = f * 8 + 2 * (lane & 3);
        size_t i0 = ((size_t)b * SQ + row0) * DM + h * DH + dh;
        size_t i8 = ((size_t)b * SQ + row0 + 8) * DM + h * DH + dh;
        *(float2*)&ctx_out[i0] = make_float2(Oacc[f][0] * inv0, Oacc[f][1] * inv0);
        *(float2*)&ctx_out[i8] = make_float2(Oacc[f][2] * inv1, Oacc[f][3] * inv1);
    }
}

extern "C" void kernel_launch(void* const* d_in, const int* in_sizes, int n_in,
                              void* d_out, int out_size) {
    const float* X    = (const float*)d_in[0];
    const float* mask = (const float*)d_in[1];
    const float* res  = (const float*)d_in[2];
    const float* Wq   = (const float*)d_in[3];
    const float* bq   = (const float*)d_in[4];
    const float* Wk   = (const float*)d_in[5];
    const float* bk   = (const float*)d_in[6];
    const float* Wv   = (const float*)d_in[7];
    const float* bv   = (const float*)d_in[8];

    float* ctx     = (float*)d_out;
    float* res_out = (float*)d_out + (size_t)NB * SQ * DM;

    dim3 g1(DM / 64, (NB * SQ) / 128, 3);
    qkv_kernel<<<g1, 256>>>(X, Wq, bq, Wk, bk, Wv, bv);

    dim3 g2(SQ / 128, NH, NB);
    attn_kernel<<<g2, 256>>>(res, mask, ctx, res_out);
}